// round 6
// baseline (speedup 1.0000x reference)
#include <cuda_runtime.h>
#include <math.h>

#define EPSV 1e-5f
#define VFLOOR 1e-6f

// Fixed shape: B=4, L=4096, D=2048, G=16 (gs=128). Chunk = 32 rows.
constexpr int Lc  = 4096;
constexpr int Gc  = 16;
constexpr int Dc  = 2048;
constexpr int CH  = 32;
constexpr int NCH = Lc / CH;      // 128
constexpr int MAXB = 8;

// decoupled-lookback state
__device__ float d_aggS [MAXB*NCH*Gc];
__device__ float d_prefS[MAXB*NCH*Gc];
__device__ float d_aggC [MAXB*NCH];
__device__ float d_prefC[MAXB*NCH];
__device__ float d_aggD [MAXB*NCH*Gc];
__device__ float d_prefD[MAXB*NCH*Gc];
__device__ int   d_flag1[MAXB*NCH];
__device__ int   d_flag2[MAXB*NCH];

__global__ void k_init(int n) {
    int i = blockIdx.x * blockDim.x + threadIdx.x;
    if (i < n) { d_flag1[i] = 0; d_flag2[i] = 0; }
}

__device__ __forceinline__ int ld_acq(const int* p) {
    int v;
    asm volatile("ld.acquire.gpu.global.b32 %0, [%1];" : "=r"(v) : "l"(p));
    return v;
}
__device__ __forceinline__ void st_rel(int* p, int v) {
    asm volatile("st.release.gpu.global.b32 [%0], %1;" :: "l"(p), "r"(v) : "memory");
}

__global__ void __launch_bounds__(512)
k_fused(const float* __restrict__ x,
        const int*   __restrict__ pcnt,
        const float* __restrict__ pmean,
        const float* __restrict__ pvar,
        const int*   __restrict__ pmask,   // bool stored as int32
        const float* __restrict__ wgt,
        const float* __restrict__ bias,
        float*       __restrict__ outF,
        int B, int writeTail, long long tailOff)
{
    const int b    = blockIdx.x / NCH;
    const int ch   = blockIdx.x % NCH;
    const int tid  = threadIdx.x;
    const int lane = tid & 31;
    const int wid  = tid >> 5;            // warp = group g
    const unsigned FULL = 0xffffffffu;
    const int rowBase = b * Lc + ch * CH; // first (b,l) row of this chunk
    const int base    = b * NCH;

    __shared__ float gm     [CH][Gc + 1];
    __shared__ float sm_mean[CH][Gc + 1];
    __shared__ float sm_rstd[CH][Gc + 1];

    const float4* xr = (const float4*)x;

    // ---------------- Phase A: group means (4-row unroll for MLP) ----------
    for (int r0 = 0; r0 < CH; r0 += 4) {
        float4 v[4];
        #pragma unroll
        for (int k = 0; k < 4; k++)
            v[k] = xr[(size_t)(rowBase + r0 + k) * (Dc / 4) + wid * 32 + lane];
        #pragma unroll
        for (int k = 0; k < 4; k++) {
            float s = (v[k].x + v[k].y) + (v[k].z + v[k].w);
            #pragma unroll
            for (int o = 16; o > 0; o >>= 1)
                s += __shfl_down_sync(FULL, s, o);
            if (lane == 0) gm[r0 + k][wid] = s * (1.0f / 128.0f);
        }
    }
    __syncthreads();

    // ---------------- Phase B: scans + lookback ----------------------------
    const int g = wid;
    const float pc     = (float)pcnt[b];
    const float pmeanv = pmean[b * Gc + g];
    const float pvarv  = pvar [b * Gc + g];
    const float psum   = pmeanv * pc;
    const float pm2    = pvarv * fmaxf(pc, 1.0f);

    const float gmv = gm[lane][g];
    const float vd  = pmask[rowBase + lane] ? 1.0f : 0.0f;
    const float s0  = gmv * vd;

    // warp inclusive scan of (gm*valid, valid) over the 32 rows
    float ls = s0, lcc = vd;
    #pragma unroll
    for (int o = 1; o < 32; o <<= 1) {
        const float a = __shfl_up_sync(FULL, ls,  o);
        const float c = __shfl_up_sync(FULL, lcc, o);
        if (lane >= o) { ls += a; lcc += c; }
    }
    const float aggSv = __shfl_sync(FULL, ls,  31);
    const float aggCv = __shfl_sync(FULL, lcc, 31);

    float exS = 0.0f, exC = 0.0f;
    if (ch == 0) {
        if (lane == 0) { d_prefS[base * Gc + g] = aggSv; if (g == 0) d_prefC[base] = aggCv; }
        __threadfence();
        __syncthreads();
        if (tid == 0) st_rel(&d_flag1[base], 2);
    } else {
        if (lane == 0) { d_aggS[(base + ch) * Gc + g] = aggSv; if (g == 0) d_aggC[base + ch] = aggCv; }
        __threadfence();
        __syncthreads();
        if (tid == 0) st_rel(&d_flag1[base + ch], 1);

        // windowed lookback (32 predecessors per window, per warp)
        int j = ch - 1;
        for (;;) {
            const int jj = j - lane;
            int f;
            for (;;) {
                f = (jj >= 0) ? ld_acq(&d_flag1[base + jj]) : 2;
                if (!__any_sync(FULL, f == 0)) break;
                __nanosleep(40);
            }
            const unsigned pb = __ballot_sync(FULL, f == 2);
            const int pl = pb ? (__ffs(pb) - 1) : 32;
            float vS = 0.0f, vC = 0.0f;
            if (lane < pl)                    { vS = d_aggS [(base + jj) * Gc + g]; vC = d_aggC [base + jj]; }
            else if (lane == pl && jj >= 0)   { vS = d_prefS[(base + jj) * Gc + g]; vC = d_prefC[base + jj]; }
            #pragma unroll
            for (int o = 16; o > 0; o >>= 1) {
                vS += __shfl_down_sync(FULL, vS, o);
                vC += __shfl_down_sync(FULL, vC, o);
            }
            exS += __shfl_sync(FULL, vS, 0);
            exC += __shfl_sync(FULL, vC, 0);
            if (pl < 32) break;
            j -= 32;
        }
        if (lane == 0) { d_prefS[(base + ch) * Gc + g] = exS + aggSv; if (g == 0) d_prefC[base + ch] = exC + aggCv; }
        __threadfence();
        __syncthreads();
        if (tid == 0) st_rel(&d_flag1[base + ch], 2);
    }

    // means
    const float S       = exS + ls;
    const float Cl      = exC + lcc;
    const float count_t = pc + Cl;
    const float mean_t  = (count_t > 0.0f) ? (psum + S) / fmaxf(count_t, 1.0f) : pmeanv;
    const float Sx = S - s0, Cx = Cl - vd;
    const float cp = pc + Cx;
    const float mean_p = (cp > 0.0f) ? (psum + Sx) / fmaxf(cp, 1.0f) : pmeanv;
    const float dd = (gmv - mean_p) * (gmv - mean_t) * vd;

    // warp inclusive scan of dd
    float ldd = dd;
    #pragma unroll
    for (int o = 1; o < 32; o <<= 1) {
        const float a = __shfl_up_sync(FULL, ldd, o);
        if (lane >= o) ldd += a;
    }
    const float aggDv = __shfl_sync(FULL, ldd, 31);

    float exD = 0.0f;
    if (ch == 0) {
        if (lane == 0) d_prefD[base * Gc + g] = aggDv;
        __threadfence();
        __syncthreads();
        if (tid == 0) st_rel(&d_flag2[base], 2);
    } else {
        if (lane == 0) d_aggD[(base + ch) * Gc + g] = aggDv;
        __threadfence();
        __syncthreads();
        if (tid == 0) st_rel(&d_flag2[base + ch], 1);

        int j = ch - 1;
        for (;;) {
            const int jj = j - lane;
            int f;
            for (;;) {
                f = (jj >= 0) ? ld_acq(&d_flag2[base + jj]) : 2;
                if (!__any_sync(FULL, f == 0)) break;
                __nanosleep(40);
            }
            const unsigned pb = __ballot_sync(FULL, f == 2);
            const int pl = pb ? (__ffs(pb) - 1) : 32;
            float vD = 0.0f;
            if (lane < pl)                  vD = d_aggD [(base + jj) * Gc + g];
            else if (lane == pl && jj >= 0) vD = d_prefD[(base + jj) * Gc + g];
            #pragma unroll
            for (int o = 16; o > 0; o >>= 1)
                vD += __shfl_down_sync(FULL, vD, o);
            exD += __shfl_sync(FULL, vD, 0);
            if (pl < 32) break;
            j -= 32;
        }
        if (lane == 0) d_prefD[(base + ch) * Gc + g] = exD + aggDv;
        __threadfence();
        __syncthreads();
        if (tid == 0) st_rel(&d_flag2[base + ch], 2);
    }

    const float m2  = pm2 + exD + ldd;
    float var = (count_t > 0.0f) ? m2 / fmaxf(count_t, 1.0f) : pvarv;
    var = fmaxf(var, VFLOOR);

    sm_mean[lane][g] = mean_t;
    sm_rstd[lane][g] = rsqrtf(var + EPSV);

    if (writeTail && ch == NCH - 1 && lane == 31) {
        outF[tailOff + B + b * Gc + g]                     = mean_t;
        outF[tailOff + B + (size_t)B * Gc + b * Gc + g]    = var;
        if (g == 0) outF[tailOff + b] = count_t;   // new_count
    }
    __syncthreads();

    // ---------------- Phase C: normalize + affine (x re-read hits L2) ------
    float4 wv = ((const float4*)wgt)[wid * 32 + lane];
    float4 bv = ((const float4*)bias)[wid * 32 + lane];
    wv.x += 1.0f; wv.y += 1.0f; wv.z += 1.0f; wv.w += 1.0f;
    float4* yr = (float4*)outF;

    for (int r0 = 0; r0 < CH; r0 += 4) {
        float4 v[4];
        #pragma unroll
        for (int k = 0; k < 4; k++)
            v[k] = xr[(size_t)(rowBase + r0 + k) * (Dc / 4) + wid * 32 + lane];
        #pragma unroll
        for (int k = 0; k < 4; k++) {
            const float mn = sm_mean[r0 + k][wid];
            const float rs = sm_rstd[r0 + k][wid];
            float4 o;
            o.x = (v[k].x - mn) * rs * wv.x + bv.x;
            o.y = (v[k].y - mn) * rs * wv.y + bv.y;
            o.z = (v[k].z - mn) * rs * wv.z + bv.z;
            o.w = (v[k].w - mn) * rs * wv.w + bv.w;
            yr[(size_t)(rowBase + r0 + k) * (Dc / 4) + wid * 32 + lane] = o;
        }
    }
}

// ---------------------------------------------------------------------------
extern "C" void kernel_launch(void* const* d_in, const int* in_sizes, int n_in,
                              void* d_out, int out_size)
{
    const float* x     = (const float*)d_in[0];
    const int*   pcnt  = (const int*)d_in[1];
    const float* pmean = (const float*)d_in[2];
    const float* pvar  = (const float*)d_in[3];
    const int*   pmask = (const int*)d_in[4];
    const float* wgt   = (const float*)d_in[5];
    const float* bias  = (const float*)d_in[6];
    float*       outF  = (float*)d_out;

    const int B = in_sizes[1];
    const int G = in_sizes[2] / B;     // 16
    const int D = in_sizes[5];         // 2048
    const int L = in_sizes[4] / B;     // 4096
    (void)G; (void)D; (void)L;

    const long long BLD = (long long)B * L * D;
    const long long expected = BLD + B + 2LL * B * G;
    const int writeTail = (out_size >= expected) ? 1 : 0;

    const int nflags = B * NCH;
    k_init<<<(nflags + 511) / 512, 512>>>(nflags);
    k_fused<<<B * NCH, 512>>>(x, pcnt, pmean, pvar, pmask, wgt, bias,
                              outF, B, writeTail, BLD);
}

// round 7
// speedup vs baseline: 1.0413x; 1.0413x over previous
#include <cuda_runtime.h>
#include <math.h>

#define EPSV 1e-5f
#define VFLOOR 1e-6f

// Fixed shape: B=4, L=4096, D=2048, G=16 (gs=128). Chunk = 8 rows.
constexpr int Lc   = 4096;
constexpr int Gc   = 16;
constexpr int Dc   = 2048;
constexpr int CH   = 8;
constexpr int NCH  = Lc / CH;     // 512 chunks per batch
constexpr int MAXB = 8;

// chunk aggregates + exclusive prefixes
__device__ float d_S [MAXB * Gc * NCH];
__device__ float d_Q [MAXB * Gc * NCH];
__device__ float d_C [MAXB * NCH];
__device__ float d_pS[MAXB * Gc * NCH];
__device__ float d_pQ[MAXB * Gc * NCH];
__device__ float d_pC[MAXB * NCH];

// ---------------------------------------------------------------------------
// K1: per-chunk aggregates. Block = one 8-row chunk; warp g reduces group g.
// 8 independent float4 loads per thread -> MLP=8.
// ---------------------------------------------------------------------------
__global__ void __launch_bounds__(512)
k_agg(const float* __restrict__ x, const int* __restrict__ pmask)
{
    const unsigned FULL = 0xffffffffu;
    const int b    = blockIdx.x >> 9;        // / NCH
    const int ch   = blockIdx.x & (NCH - 1);
    const int lane = threadIdx.x & 31;
    const int g    = threadIdx.x >> 5;
    const int rowBase = b * Lc + ch * CH;

    const float4* xr = (const float4*)x;
    float4 v[CH];
    #pragma unroll
    for (int r = 0; r < CH; r++)
        v[r] = xr[(size_t)(rowBase + r) * (Dc / 4) + g * 32 + lane];

    float S = 0.f, Q = 0.f, C = 0.f;
    #pragma unroll
    for (int r = 0; r < CH; r++) {
        float s = (v[r].x + v[r].y) + (v[r].z + v[r].w);
        #pragma unroll
        for (int o = 16; o > 0; o >>= 1)
            s += __shfl_xor_sync(FULL, s, o);
        const float gm = s * (1.0f / 128.0f);
        const float vr = pmask[rowBase + r] ? 1.0f : 0.0f;
        S += gm * vr;
        Q += gm * gm * vr;
        C += vr;
    }
    if (lane == 0) {
        const int idx = (b * Gc + g) * NCH + ch;
        d_S[idx] = S;
        d_Q[idx] = Q;
        if (g == 0) d_C[b * NCH + ch] = C;
    }
}

// ---------------------------------------------------------------------------
// K1.5: exclusive scan of chunk aggregates. Grid = B; warp g scans (b,g).
// ---------------------------------------------------------------------------
__global__ void __launch_bounds__(512)
k_scanagg()
{
    const unsigned FULL = 0xffffffffu;
    const int b    = blockIdx.x;
    const int lane = threadIdx.x & 31;
    const int g    = threadIdx.x >> 5;

    const int base = (b * Gc + g) * NCH;
    float cs = 0.f, cq = 0.f;
    for (int t = 0; t < NCH / 32; t++) {
        const int i = t * 32 + lane;
        const float s0 = d_S[base + i];
        const float q0 = d_Q[base + i];
        float is = s0, iq = q0;
        #pragma unroll
        for (int o = 1; o < 32; o <<= 1) {
            const float a = __shfl_up_sync(FULL, is, o);
            const float c = __shfl_up_sync(FULL, iq, o);
            if (lane >= o) { is += a; iq += c; }
        }
        d_pS[base + i] = cs + is - s0;
        d_pQ[base + i] = cq + iq - q0;
        cs += __shfl_sync(FULL, is, 31);
        cq += __shfl_sync(FULL, iq, 31);
    }
    if (g == 0) {
        const int cb = b * NCH;
        float cc = 0.f;
        for (int t = 0; t < NCH / 32; t++) {
            const int i = t * 32 + lane;
            const float c0 = d_C[cb + i];
            float ic = c0;
            #pragma unroll
            for (int o = 1; o < 32; o <<= 1) {
                const float a = __shfl_up_sync(FULL, ic, o);
                if (lane >= o) ic += a;
            }
            d_pC[cb + i] = cc + ic - c0;
            cc += __shfl_sync(FULL, ic, 31);
        }
    }
}

// ---------------------------------------------------------------------------
// K2: map. Block = one 8-row chunk; x chunk held in registers; closed-form
// Welford stats from (S,Q,C) prefixes; normalize from registers; no smem.
// ---------------------------------------------------------------------------
__global__ void __launch_bounds__(512)
k_norm(const float* __restrict__ x,
       const int*   __restrict__ pcnt,
       const float* __restrict__ pmean,
       const float* __restrict__ pvar,
       const int*   __restrict__ pmask,
       const float* __restrict__ wgt,
       const float* __restrict__ bias,
       float*       __restrict__ outF,
       int B, int writeTail, long long tailOff)
{
    const unsigned FULL = 0xffffffffu;
    const int b    = blockIdx.x >> 9;
    const int ch   = blockIdx.x & (NCH - 1);
    const int lane = threadIdx.x & 31;
    const int g    = threadIdx.x >> 5;
    const int rowBase = b * Lc + ch * CH;

    const float4* xr = (const float4*)x;
    float4 v[CH];
    #pragma unroll
    for (int r = 0; r < CH; r++)
        v[r] = xr[(size_t)(rowBase + r) * (Dc / 4) + g * 32 + lane];

    // affine params (independent loads, overlap with x)
    float4 wv = ((const float4*)wgt)[g * 32 + lane];
    float4 bv = ((const float4*)bias)[g * 32 + lane];
    wv.x += 1.f; wv.y += 1.f; wv.z += 1.f; wv.w += 1.f;

    const float pc     = (float)pcnt[b];
    const float pmeanv = pmean[b * Gc + g];
    const float pvarv  = pvar [b * Gc + g];
    const float psum   = pmeanv * pc;
    const float pm2    = pvarv * fmaxf(pc, 1.0f);

    const int aidx = (b * Gc + g) * NCH + ch;
    const float prefS = d_pS[aidx];
    const float prefQ = d_pQ[aidx];
    const float prefC = d_pC[b * NCH + ch];

    // group means; lane r keeps row r's gm
    float mygm = 0.f;
    #pragma unroll
    for (int r = 0; r < CH; r++) {
        float s = (v[r].x + v[r].y) + (v[r].z + v[r].w);
        #pragma unroll
        for (int o = 16; o > 0; o >>= 1)
            s += __shfl_xor_sync(FULL, s, o);
        const float gm = s * (1.0f / 128.0f);
        if (lane == r) mygm = gm;
    }
    const float myv = (lane < CH) ? (pmask[rowBase + (lane & (CH - 1))] ? 1.0f : 0.0f) : 0.0f;

    // inclusive scan over the 8 rows (lanes 0..7)
    float sS = mygm * myv;
    float sQ = mygm * mygm * myv;
    float sC = myv;
    #pragma unroll
    for (int o = 1; o < CH; o <<= 1) {
        const float a0 = __shfl_up_sync(FULL, sS, o);
        const float a1 = __shfl_up_sync(FULL, sQ, o);
        const float a2 = __shfl_up_sync(FULL, sC, o);
        if (lane >= o) { sS += a0; sQ += a1; sC += a2; }
    }

    // closed-form streaming stats (lanes 0..7 hold rows 0..7)
    const float S_t = prefS + sS;
    const float Q_t = prefQ + sQ;
    const float c_t = prefC + sC;                 // batch valid count up to row
    const float count_t = pc + c_t;

    float mean_t = pmeanv, var = pvarv;
    if (count_t > 0.0f) {
        mean_t = (psum + S_t) / fmaxf(count_t, 1.0f);
        float sumdd = 0.0f;
        if (c_t > 0.0f) {
            const float bm  = S_t / c_t;
            const float m2b = Q_t - bm * S_t;                    // batch M2
            const float dlt = bm - pmeanv;
            sumdd = m2b + dlt * dlt * (pc * c_t / (pc + c_t));   // Chan merge
        }
        var = (pm2 + sumdd) / fmaxf(count_t, 1.0f);
    }
    var = fmaxf(var, VFLOOR);
    const float myrstd = rsqrtf(var + EPSV);

    if (writeTail && ch == NCH - 1 && lane == CH - 1) {
        outF[tailOff + B + b * Gc + g]                  = mean_t;
        outF[tailOff + B + (size_t)B * Gc + b * Gc + g] = var;
        if (g == 0) outF[tailOff + b] = count_t;   // new_count
    }

    // normalize from registers; stats broadcast by shuffle
    float4* yr = (float4*)outF;
    #pragma unroll
    for (int r = 0; r < CH; r++) {
        const float mn = __shfl_sync(FULL, mean_t, r);
        const float rs = __shfl_sync(FULL, myrstd, r);
        float4 o;
        o.x = (v[r].x - mn) * rs * wv.x + bv.x;
        o.y = (v[r].y - mn) * rs * wv.y + bv.y;
        o.z = (v[r].z - mn) * rs * wv.z + bv.z;
        o.w = (v[r].w - mn) * rs * wv.w + bv.w;
        yr[(size_t)(rowBase + r) * (Dc / 4) + g * 32 + lane] = o;
    }
}

// ---------------------------------------------------------------------------
extern "C" void kernel_launch(void* const* d_in, const int* in_sizes, int n_in,
                              void* d_out, int out_size)
{
    const float* x     = (const float*)d_in[0];
    const int*   pcnt  = (const int*)d_in[1];
    const float* pmean = (const float*)d_in[2];
    const float* pvar  = (const float*)d_in[3];
    const int*   pmask = (const int*)d_in[4];
    const float* wgt   = (const float*)d_in[5];
    const float* bias  = (const float*)d_in[6];
    float*       outF  = (float*)d_out;

    const int B = in_sizes[1];
    const int G = in_sizes[2] / B;     // 16
    const int D = in_sizes[5];         // 2048
    const int L = in_sizes[4] / B;     // 4096
    (void)G; (void)D; (void)L;

    const long long BLD = (long long)B * L * D;
    const long long expected = BLD + B + 2LL * B * G;
    const int writeTail = (out_size >= expected) ? 1 : 0;

    k_agg    <<<B * NCH, 512>>>(x, pmask);
    k_scanagg<<<B, 512>>>();
    k_norm   <<<B * NCH, 512>>>(x, pcnt, pmean, pvar, pmask, wgt, bias,
                                outF, B, writeTail, BLD);
}

// round 8
// speedup vs baseline: 1.5296x; 1.4690x over previous
#include <cuda_runtime.h>
#include <math.h>

#define EPSV 1e-5f
#define VFLOOR 1e-6f

// Fixed shape: B=4, L=4096, D=2048, G=16 (gs=128).
constexpr int Lc  = 4096;
constexpr int Gc  = 16;
constexpr int Dc  = 2048;
constexpr int CH  = 8;
constexpr int NCH = Lc / CH;      // 512
constexpr int MAXB = 8;

__device__ float  g_gmT [MAXB * Gc * Lc];   // (b,g,l) group means
__device__ float2 g_stat[MAXB * Gc * Lc];   // (b,g,l) {mean, rstd}

// ---------------------------------------------------------------------------
// K1: group means only. Block = 8-row chunk; warp g reduces group g per row.
// All-lane xor-reduce; lanes 0..7 store 8 consecutive gm (one 32B store).
// ---------------------------------------------------------------------------
__global__ void __launch_bounds__(512)
k_gm(const float* __restrict__ x)
{
    const unsigned FULL = 0xffffffffu;
    const int b    = blockIdx.x >> 9;
    const int ch   = blockIdx.x & (NCH - 1);
    const int lane = threadIdx.x & 31;
    const int g    = threadIdx.x >> 5;
    const int rowBase = b * Lc + ch * CH;

    const float4* xr = (const float4*)x;
    float4 v[CH];
    #pragma unroll
    for (int r = 0; r < CH; r++)
        v[r] = xr[(size_t)(rowBase + r) * (Dc / 4) + g * 32 + lane];

    float mygm = 0.0f;
    #pragma unroll
    for (int r = 0; r < CH; r++) {
        float s = (v[r].x + v[r].y) + (v[r].z + v[r].w);
        #pragma unroll
        for (int o = 16; o > 0; o >>= 1)
            s += __shfl_xor_sync(FULL, s, o);
        if (lane == r) mygm = s * (1.0f / 128.0f);
    }
    if (lane < CH)
        g_gmT[(b * Gc + g) * Lc + ch * CH + lane] = mygm;
}

// ---------------------------------------------------------------------------
// K2: per-(b,g) sequential-Welford scan over L (proven R2 math).
// 64 blocks, 512 threads, 8 elems/thread. Emits (mean,rstd) float2 + tail.
// ---------------------------------------------------------------------------
__global__ void __launch_bounds__(512)
k_scan(const int* __restrict__ prev_count,
       const float* __restrict__ prev_mean,
       const float* __restrict__ prev_var,
       const int* __restrict__ pmask,
       float* __restrict__ outF,
       int B, int writeTail, long long tailOff)
{
    constexpr int P = 8;
    const int b = blockIdx.x / Gc;
    const int g = blockIdx.x - b * Gc;
    const int tid  = threadIdx.x;
    const int lane = tid & 31;
    const int wid  = tid >> 5;
    const unsigned FULL = 0xffffffffu;

    const float pc    = (float)prev_count[b];
    const float pmean = prev_mean[b * Gc + g];
    const float pvar  = prev_var[b * Gc + g];
    const float psum  = pmean * pc;
    const float pm2   = pvar * fmaxf(pc, 1.0f);

    __shared__ float smS[16], smC[16];

    const float* gmrow = &g_gmT[(b * Gc + g) * Lc];

    // load + thread-local inclusive scan of (gm*valid, valid)
    float gv[P], vv[P], ls[P], lc[P];
    float sa = 0.f, ca = 0.f;
    #pragma unroll
    for (int j = 0; j < P; j++) {
        const int l = tid * P + j;
        const float gmv = gmrow[l];
        const float vd  = pmask[b * Lc + l] ? 1.0f : 0.0f;
        gv[j] = gmv; vv[j] = vd;
        sa += gmv * vd;  ca += vd;
        ls[j] = sa;      lc[j] = ca;
    }

    float ws = sa, wc = ca;
    #pragma unroll
    for (int o = 1; o < 32; o <<= 1) {
        const float ns = __shfl_up_sync(FULL, ws, o);
        const float nc = __shfl_up_sync(FULL, wc, o);
        if (lane >= o) { ws += ns; wc += nc; }
    }
    const float exs = ws - sa, exc = wc - ca;

    if (lane == 31) { smS[wid] = ws; smC[wid] = wc; }
    __syncthreads();
    if (tid == 0) {
        float rs = 0.f, rc = 0.f;
        #pragma unroll
        for (int i = 0; i < 16; i++) {
            const float ts = smS[i], tc = smC[i];
            smS[i] = rs; smC[i] = rc;
            rs += ts; rc += tc;
        }
    }
    __syncthreads();
    const float baseS = smS[wid] + exs;
    const float baseC = smC[wid] + exc;

    float ddv[P], meanv[P], countv[P];
    #pragma unroll
    for (int j = 0; j < P; j++) {
        const float S = baseS + ls[j];
        const float C = baseC + lc[j];
        const float count_t = pc + C;
        const float mean_t  = (count_t > 0.f) ? (psum + S) / fmaxf(count_t, 1.f) : pmean;
        const float exS2 = S - gv[j] * vv[j];
        const float exC2 = C - vv[j];
        const float cp = pc + exC2;
        const float mean_p = (cp > 0.f) ? (psum + exS2) / fmaxf(cp, 1.f) : pmean;
        ddv[j]   = (gv[j] - mean_p) * (gv[j] - mean_t) * vv[j];
        meanv[j] = mean_t;
        countv[j] = count_t;
    }
    __syncthreads();

    float ld[P];
    float da = 0.f;
    #pragma unroll
    for (int j = 0; j < P; j++) { da += ddv[j]; ld[j] = da; }
    float wd = da;
    #pragma unroll
    for (int o = 1; o < 32; o <<= 1) {
        const float nd = __shfl_up_sync(FULL, wd, o);
        if (lane >= o) wd += nd;
    }
    const float exd = wd - da;
    if (lane == 31) smS[wid] = wd;
    __syncthreads();
    if (tid == 0) {
        float rd = 0.f;
        #pragma unroll
        for (int i = 0; i < 16; i++) { const float td = smS[i]; smS[i] = rd; rd += td; }
    }
    __syncthreads();
    const float baseD = smS[wid] + exd;

    float2* statrow = &g_stat[(size_t)(b * Gc + g) * Lc];
    #pragma unroll
    for (int j = 0; j < P; j++) {
        const int l = tid * P + j;
        const float m2 = pm2 + baseD + ld[j];
        float var = (countv[j] > 0.f) ? m2 / fmaxf(countv[j], 1.f) : pvar;
        var = fmaxf(var, VFLOOR);
        statrow[l] = make_float2(meanv[j], rsqrtf(var + EPSV));
        if (writeTail && l == Lc - 1) {
            outF[tailOff + B + b * Gc + g]                  = meanv[j];
            outF[tailOff + B + (size_t)B * Gc + b * Gc + g] = var;
            if (g == 0) outF[tailOff + b] = countv[j];
        }
    }
}

// ---------------------------------------------------------------------------
// K3: pure elementwise normalize. 4 float4/thread strided by one row so each
// warp stays inside a single group-row; stat = broadcast float2 per k.
// ---------------------------------------------------------------------------
__global__ void __launch_bounds__(512)
k_norm(const float* __restrict__ x,
       const float* __restrict__ wgt,
       const float* __restrict__ bias,
       float* __restrict__ outF)
{
    constexpr int NV = 4;
    const int tid = threadIdx.x;
    const long long idx0 = (long long)blockIdx.x * (512 * NV) + tid;

    const int d4 = (int)(idx0 & 511);            // invariant across k (stride 512)
    float4 wv = ((const float4*)wgt)[d4];
    float4 bv = ((const float4*)bias)[d4];
    wv.x += 1.f; wv.y += 1.f; wv.z += 1.f; wv.w += 1.f;

    const float4* xr = (const float4*)x;
    float4* yr = (float4*)outF;

    float4 v[NV];
    float2 st[NV];
    #pragma unroll
    for (int k = 0; k < NV; k++) {
        const long long idx = idx0 + (long long)k * 512;
        v[k] = xr[idx];
        const int row = (int)(idx >> 9);         // b*Lc + l
        const int g   = ((int)idx >> 5) & 15;
        const int b   = row >> 12;
        const int l   = row & (Lc - 1);
        st[k] = g_stat[((size_t)(b * Gc + g)) * Lc + l];
    }
    #pragma unroll
    for (int k = 0; k < NV; k++) {
        const long long idx = idx0 + (long long)k * 512;
        const float mn = st[k].x, rs = st[k].y;
        float4 o;
        o.x = (v[k].x - mn) * rs * wv.x + bv.x;
        o.y = (v[k].y - mn) * rs * wv.y + bv.y;
        o.z = (v[k].z - mn) * rs * wv.z + bv.z;
        o.w = (v[k].w - mn) * rs * wv.w + bv.w;
        yr[idx] = o;
    }
}

// ---------------------------------------------------------------------------
extern "C" void kernel_launch(void* const* d_in, const int* in_sizes, int n_in,
                              void* d_out, int out_size)
{
    const float* x     = (const float*)d_in[0];
    const int*   pcnt  = (const int*)d_in[1];
    const float* pmean = (const float*)d_in[2];
    const float* pvar  = (const float*)d_in[3];
    const int*   pmask = (const int*)d_in[4];
    const float* wgt   = (const float*)d_in[5];
    const float* bias  = (const float*)d_in[6];
    float*       outF  = (float*)d_out;

    const int B = in_sizes[1];
    const int G = in_sizes[2] / B;     // 16
    const int D = in_sizes[5];         // 2048
    const int L = in_sizes[4] / B;     // 4096
    (void)G; (void)D; (void)L;

    const long long BLD = (long long)B * L * D;
    const long long expected = BLD + B + 2LL * B * G;
    const int writeTail = (out_size >= expected) ? 1 : 0;

    k_gm  <<<B * NCH, 512>>>(x);
    k_scan<<<B * Gc, 512>>>(pcnt, pmean, pvar, pmask, outF, B, writeTail, BLD);

    const long long n4 = BLD / 4;                 // 8M float4
    const int blocks = (int)(n4 / (512 * 4));     // 4096
    k_norm<<<blocks, 512>>>(x, wgt, bias, outF);
}